// round 14
// baseline (speedup 1.0000x reference)
#include <cuda_runtime.h>
#include <math.h>

#define B_    4
#define NPTS  8192
#define KNN   9
#define TPB   256
#define QPBK  256                  // queries per knn block
#define KTPB  512                  // 2 threads (sides) per query
#define PAD   8
#define CAPS  64                   // record capacity per (query, side)
#define BNDMAX 1e37f
#define KB_   2048                 // counting-sort buckets
#define NPOINTS (B_*NPTS)          // 32768
#define NROWS   (NPOINTS*KNN)      // 294912
#define NB1     (NPOINTS/TPB)      // 128
#define NB3     (NROWS/TPB)        // 1152
#define EPS_BN  1e-5f

// ---- scratch (static device memory; no allocations) ----
__device__ float4   g_sp[NPOINTS];                   // sorted points (x,y,z,|p|^2)
__device__ int      g_sid[NPOINTS];                  // sorted pos -> original id
__device__ unsigned g_rec[(size_t)NPOINTS*2*CAPS];   // insert-event records per side
__device__ int      g_nbr[(size_t)NPOINTS*KNN];
__device__ __align__(16) float g_h1[(size_t)NROWS*10];
__device__ __align__(16) float g_h2[(size_t)NROWS*10];
__device__ float g_part1[NB1*20];
__device__ float g_part2[NB3*20];
__device__ float g_coef1[20];
__device__ float g_coef2[20];
__device__ int   g_dummy;

// branchless insert of one value into sorted-ascending s[0..9] (values only)
#define CHAIN_INSERT(sarr, val) do {                 \
    float _c = (val);                                \
    _Pragma("unroll")                                \
    for (int _j = 0; _j < 10; _j++) {                \
        float _lo = fminf(sarr[_j], _c);             \
        _c = fmaxf(sarr[_j], _c);                    \
        sarr[_j] = _lo;                              \
    }                                                \
} while (0)

// exact lexicographic (value, id) insert into ascending (v, vid)[0..9]
__device__ __forceinline__ void lex_insert(float* v, int* vid, float sv, int oid) {
    if (sv < v[9] || (sv == v[9] && oid < vid[9])) {
        float cs = sv; int ci = oid;
        #pragma unroll
        for (int j = 0; j < 10; j++) {
            bool take = (cs < v[j]) || (cs == v[j] && ci < vid[j]);
            float tv = take ? cs : v[j];
            float uv = take ? v[j] : cs;
            int   ti = take ? ci : vid[j];
            int   ui = take ? vid[j] : ci;
            v[j] = tv; vid[j] = ti; cs = uv; ci = ui;
        }
    }
}

// no-op slot-shifter so ncu's fixed capture slot lands on k_knn
__global__ void k_nop() {
    if (threadIdx.x == 1024) g_dummy = 1;
}

// =====================================================================
// Kernel 0: per-batch COUNTING sort by x (exact final order by (x,id))
// =====================================================================
__global__ void __launch_bounds__(1024) k_csort(const float* __restrict__ x)
{
    extern __shared__ unsigned char smem_raw[];
    unsigned*       hist  = (unsigned*)smem_raw;               // [KB_]
    unsigned*       offs  = hist + KB_;                        // [KB_]
    unsigned*       cur   = offs + KB_;                        // [KB_]
    unsigned*       chunk = cur  + KB_;                        // [32]
    float*          keyx  = (float*)(chunk + 32);              // [NPTS]
    unsigned short* kid   = (unsigned short*)(keyx + NPTS);    // [NPTS]

    const int b = blockIdx.x;
    const int t = threadIdx.x;
    const float* xb = x + (size_t)b*NPTS*3;

    for (int i = t; i < KB_; i += 1024) { hist[i] = 0u; cur[i] = 0u; }
    __syncthreads();

    const float lo = -6.f;
    const float invw = (float)KB_ / 12.f;

    for (int i = t; i < NPTS; i += 1024) {
        float px = xb[3*i];
        int bi = (int)floorf((px - lo) * invw);
        bi = min(max(bi, 0), KB_-1);
        atomicAdd(&hist[bi], 1u);
    }
    __syncthreads();

    if (t < 32) {
        unsigned s = 0;
        for (int j = 0; j < 64; j++) s += hist[t*64 + j];
        chunk[t] = s;
    }
    __syncthreads();
    if (t == 0) {
        unsigned s = 0;
        for (int j = 0; j < 32; j++) { unsigned c = chunk[j]; chunk[j] = s; s += c; }
    }
    __syncthreads();
    if (t < 32) {
        unsigned s = chunk[t];
        for (int j = 0; j < 64; j++) { unsigned c = hist[t*64 + j]; offs[t*64 + j] = s; s += c; }
    }
    __syncthreads();

    for (int i = t; i < NPTS; i += 1024) {
        float px = xb[3*i];
        int bi = (int)floorf((px - lo) * invw);
        bi = min(max(bi, 0), KB_-1);
        unsigned slot = offs[bi] + atomicAdd(&cur[bi], 1u);
        keyx[slot] = px;
        kid[slot]  = (unsigned short)i;
    }
    __syncthreads();

    for (int bb = t; bb < KB_; bb += 1024) {
        int s0 = (int)offs[bb];
        int s1 = s0 + (int)hist[bb];
        for (int i2 = s0 + 1; i2 < s1; i2++) {
            float kx = keyx[i2]; unsigned short ki = kid[i2];
            int j = i2 - 1;
            while (j >= s0 && (keyx[j] > kx || (keyx[j] == kx && kid[j] > ki))) {
                keyx[j+1] = keyx[j]; kid[j+1] = kid[j]; j--;
            }
            keyx[j+1] = kx; kid[j+1] = ki;
        }
    }
    __syncthreads();

    for (int i = t; i < NPTS; i += 1024) {
        int id = (int)kid[i];
        float px = xb[3*id+0], py = xb[3*id+1], pz = xb[3*id+2];
        g_sp[(size_t)b*NPTS + i] = make_float4(px, py, pz, px*px + py*py + pz*pz);
        g_sid[(size_t)b*NPTS + i] = id;
    }
}

// =====================================================================
// Kernel A: kNN sorted-axis outward scan; 2 threads/query (R/L sides)
//           with lock-free monotone shared bound through smem.
// =====================================================================
__global__ void __launch_bounds__(KTPB, 1) k_knn()
{
    extern __shared__ unsigned char smem_raw[];
    float4*         spb  = (float4*)smem_raw;                 // [NPTS + 2*PAD]
    float4*         sp   = spb + PAD;
    unsigned short* ssid = (unsigned short*)(spb + NPTS + 2*PAD);   // [NPTS]
    float*          sBnd = (float*)(ssid + NPTS);                   // [KTPB]

    const int t    = threadIdx.x;
    const int blk  = blockIdx.x;
    const int b    = blk >> 5;
    const int pos  = (blk & 31) * QPBK + (t >> 1);
    const int side = t & 1;

    for (int i = t; i < NPTS; i += KTPB) {
        sp[i]   = g_sp[(size_t)b*NPTS + i];
        ssid[i] = (unsigned short)g_sid[(size_t)b*NPTS + i];
    }
    if (t < PAD) {
        // w=+inf: sentinel never recorded/inserted; x=2e19: dx^2=inf > bnd terminates
        float4 sent = make_float4(2e19f, 0.f, 0.f, __int_as_float(0x7f800000));
        spb[t]        = sent;
        sp[NPTS + t]  = sent;
    }
    sBnd[t] = 3.4e38f;
    __syncthreads();

    const float4 q = sp[pos];
    const float qq  = q.w;
    const float nqx = -2.f*q.x, nqy = -2.f*q.y, nqz = -2.f*q.z;

    float s[10];
    #pragma unroll
    for (int j = 0; j < 10; j++) s[j] = 3.4e38f;

    unsigned* rec = g_rec + ((size_t)(b*NPTS + pos)*2 + side)*CAPS;
    int cnt = 0;

    volatile float* vB = sBnd;
    const int dstep = side ? -1 : 1;
    int r = side ? pos - 1 : pos;

    #pragma unroll 1
    for (;;) {
        // shared monotone bound: min(own s[9], partner s[9]); stale reads
        // are >= current value -> conservative -> correct.
        float gate = fminf(s[9], vB[t ^ 1]);
        float bnd  = fminf(fmaf(gate + qq, 1.01f, 4e-6f), BNDMAX);

        float4 p0 = sp[r];
        float dx0 = p0.x - q.x;
        if (dx0*dx0 > bnd) break;            // sorted x => valid for all further

        const int d1 = dstep, d2 = 2*dstep, d3 = 3*dstep;
        const int d4 = 4*dstep, d5 = 5*dstep, d6 = 6*dstep, d7 = 7*dstep;
        float4 p1 = sp[r+d1], p2 = sp[r+d2], p3 = sp[r+d3];
        float4 p4 = sp[r+d4], p5 = sp[r+d5], p6 = sp[r+d6], p7 = sp[r+d7];
        float s0 = fmaf(p0.z,nqz,fmaf(p0.y,nqy,fmaf(p0.x,nqx,p0.w)));
        float s1 = fmaf(p1.z,nqz,fmaf(p1.y,nqy,fmaf(p1.x,nqx,p1.w)));
        float s2 = fmaf(p2.z,nqz,fmaf(p2.y,nqy,fmaf(p2.x,nqx,p2.w)));
        float s3 = fmaf(p3.z,nqz,fmaf(p3.y,nqy,fmaf(p3.x,nqx,p3.w)));
        float s4 = fmaf(p4.z,nqz,fmaf(p4.y,nqy,fmaf(p4.x,nqx,p4.w)));
        float s5 = fmaf(p5.z,nqz,fmaf(p5.y,nqy,fmaf(p5.x,nqx,p5.w)));
        float s6 = fmaf(p6.z,nqz,fmaf(p6.y,nqy,fmaf(p6.x,nqx,p6.w)));
        float s7 = fmaf(p7.z,nqz,fmaf(p7.y,nqy,fmaf(p7.x,nqx,p7.w)));
        float mn = fminf(fminf(fminf(s0,s1),fminf(s2,s3)),
                         fminf(fminf(s4,s5),fminf(s6,s7)));
        if (mn <= gate) {
            if (s0 <= gate) { if (cnt<CAPS) rec[cnt]=r;    cnt++; if (s0<s[9]) CHAIN_INSERT(s,s0); }
            if (s1 <= gate) { if (cnt<CAPS) rec[cnt]=r+d1; cnt++; if (s1<s[9]) CHAIN_INSERT(s,s1); }
            if (s2 <= gate) { if (cnt<CAPS) rec[cnt]=r+d2; cnt++; if (s2<s[9]) CHAIN_INSERT(s,s2); }
            if (s3 <= gate) { if (cnt<CAPS) rec[cnt]=r+d3; cnt++; if (s3<s[9]) CHAIN_INSERT(s,s3); }
            if (s4 <= gate) { if (cnt<CAPS) rec[cnt]=r+d4; cnt++; if (s4<s[9]) CHAIN_INSERT(s,s4); }
            if (s5 <= gate) { if (cnt<CAPS) rec[cnt]=r+d5; cnt++; if (s5<s[9]) CHAIN_INSERT(s,s5); }
            if (s6 <= gate) { if (cnt<CAPS) rec[cnt]=r+d6; cnt++; if (s6<s[9]) CHAIN_INSERT(s,s6); }
            if (s7 <= gate) { if (cnt<CAPS) rec[cnt]=r+d7; cnt++; if (s7<s[9]) CHAIN_INSERT(s,s7); }
            vB[t] = s[9];                    // publish improved bound (monotone)
        }
        r += 8*dstep;
    }

    __syncthreads();                          // records + counts visible
    const int cntP = __shfl_xor_sync(0xffffffffu, cnt, 1);

    // ---- exact selection by (value, original id) over both sides' records --
    if (side == 0) {
        float v[10]; int vid[10];
        #pragma unroll
        for (int j = 0; j < 10; j++) { v[j] = 3.4e38f; vid[j] = 0x7fffffff; }

        if (cnt <= CAPS && cntP <= CAPS) {
            const unsigned* recbase = g_rec + (size_t)(b*NPTS + pos)*2*CAPS;
            #pragma unroll 1
            for (int h = 0; h < 2; h++) {
                const unsigned* R = recbase + h*CAPS;
                const int M = h ? cntP : cnt;
                #pragma unroll 1
                for (int j2 = 0; j2 < M; j2 += 4) {           // batched (MLP=4)
                    unsigned pp0 = R[j2];
                    unsigned pp1 = (j2+1 < M) ? R[j2+1] : 0xffffffffu;
                    unsigned pp2 = (j2+2 < M) ? R[j2+2] : 0xffffffffu;
                    unsigned pp3 = (j2+3 < M) ? R[j2+3] : 0xffffffffu;
                    #pragma unroll
                    for (int u = 0; u < 4; u++) {
                        unsigned pp = u==0?pp0 : u==1?pp1 : u==2?pp2 : pp3;
                        if (pp < (unsigned)NPTS) {
                            float4 p = sp[pp];
                            float sv = fmaf(p.z,nqz,fmaf(p.y,nqy,fmaf(p.x,nqx,p.w)));
                            lex_insert(v, vid, sv, (int)ssid[pp]);
                        }
                    }
                }
            }
        } else {
            // exact fallback (deterministic; ~never taken)
            #pragma unroll 1
            for (int i = 0; i < NPTS; i++) {
                float4 p = sp[i];
                float sv = fmaf(p.z,nqz,fmaf(p.y,nqy,fmaf(p.x,nqx,p.w)));
                lex_insert(v, vid, sv, (int)ssid[i]);
            }
        }

        // rank-0 dropped by the reference ([:, :, 1:]); keep ranks 1..9
        const int qoid = (int)ssid[pos];
        int* dst = g_nbr + (size_t)(b*NPTS + qoid)*KNN;
        #pragma unroll
        for (int j = 1; j < 10; j++) dst[j-1] = vid[j];
    }
}

// =====================================================================
// Kernel B: angular features + GEMM1 + stats1
// =====================================================================
__global__ void __launch_bounds__(TPB) k_feat(const float* __restrict__ x,
                                              const float* __restrict__ W1,
                                              const float* __restrict__ b1)
{
    __shared__ float sW1[70], sB1[10], sRed[(TPB/32)*20];
    const int t = threadIdx.x;
    if (t < 70) sW1[t] = W1[t];
    if (t < 10) sB1[t] = b1[t];
    __syncthreads();

    const int p = blockIdx.x*TPB + t;
    const int b = p / NPTS;
    const int n = p % NPTS;
    const float* xb = x + (size_t)b*NPTS*3;
    const float qx = xb[3*n+0], qy = xb[3*n+1], qz = xb[3*n+2];

    const int* ids = g_nbr + (size_t)p*KNN;
    float rx[KNN], ry[KNN], rz[KNN], ph[KNN];
    #pragma unroll
    for (int j = 0; j < KNN; j++) {
        int id = ids[j];
        rx[j] = xb[3*id+0] - qx;
        ry[j] = xb[3*id+1] - qy;
        rz[j] = xb[3*id+2] - qz;
        ph[j] = atan2f(ry[j], rx[j]);
    }

    #pragma unroll
    for (int pass = 0; pass < KNN-1; pass++) {
        #pragma unroll
        for (int j = 0; j < KNN-1; j++) {
            if (j < KNN-1-pass) {
                if (ph[j+1] < ph[j]) {
                    float tt;
                    tt = ph[j]; ph[j] = ph[j+1]; ph[j+1] = tt;
                    tt = rx[j]; rx[j] = rx[j+1]; rx[j+1] = tt;
                    tt = ry[j]; ry[j] = ry[j+1]; ry[j+1] = tt;
                    tt = rz[j]; rz[j] = rz[j+1]; rz[j+1] = tt;
                }
            }
        }
    }

    float sum[10], sq[10];
    #pragma unroll
    for (int c = 0; c < 10; c++) { sum[c] = 0.f; sq[c] = 0.f; }

    float sgn = 1.f;
    const size_t rowbase = (size_t)p * KNN * 10;
    #pragma unroll
    for (int i = 0; i < KNN; i++) {
        const int i2 = (i+1) % KNN;
        float v1x = rx[i],  v1y = ry[i],  v1z = rz[i];
        float v2x = rx[i2], v2y = ry[i2], v2z = rz[i2];
        float cx = 0.5f*(v1x+v2x), cy = 0.5f*(v1y+v2y), cz = 0.5f*(v1z+v2z);
        float nx = v1y*v2z - v1z*v2y;
        float ny = v1z*v2x - v1x*v2z;
        float nz = v1x*v2y - v1y*v2x;
        float nrm = sqrtf(nx*nx + ny*ny + nz*nz);
        float inv = 1.f/(nrm + 1e-6f);
        nx *= inv; ny *= inv; nz *= inv;
        if (i == 0) sgn = (nx > 0.f) ? 1.f : -1.f;
        nx *= sgn; ny *= sgn; nz *= sgn;
        float pos7 = (nx*cx + ny*cy + nz*cz) * 0.57735026918962576f;

        float f[7] = {cx, cy, cz, nx, ny, nz, pos7};
        #pragma unroll
        for (int c = 0; c < 10; c++) {
            float h = sB1[c];
            #pragma unroll
            for (int ff = 0; ff < 7; ff++) h = fmaf(f[ff], sW1[ff*10 + c], h);
            g_h1[rowbase + i*10 + c] = h;
            sum[c] += h;
            sq[c]  = fmaf(h, h, sq[c]);
        }
    }

    #pragma unroll
    for (int c = 0; c < 10; c++) {
        #pragma unroll
        for (int o = 16; o > 0; o >>= 1) {
            sum[c] += __shfl_down_sync(0xffffffffu, sum[c], o);
            sq[c]  += __shfl_down_sync(0xffffffffu, sq[c],  o);
        }
    }
    const int warp = t >> 5, lane = t & 31;
    if (lane == 0) {
        #pragma unroll
        for (int c = 0; c < 10; c++) {
            sRed[warp*20 + c]      = sum[c];
            sRed[warp*20 + 10 + c] = sq[c];
        }
    }
    __syncthreads();
    if (t < 20) {
        float acc = 0.f;
        #pragma unroll
        for (int w = 0; w < TPB/32; w++) acc += sRed[w*20 + t];
        g_part1[blockIdx.x*20 + t] = acc;
    }
}

// =====================================================================
// Parallel BN-stats finalize
// =====================================================================
__device__ __forceinline__ void fin_body(const float* __restrict__ part, int nblk,
                                         const float* __restrict__ g,
                                         const float* __restrict__ be,
                                         float* __restrict__ coef)
{
    __shared__ float red[32*20];
    __shared__ float tot[20];
    const int t = threadIdx.x;
    const int c = t % 20, sub = t / 20;
    float acc = 0.f;
    for (int k = sub; k < nblk; k += 32) acc += part[k*20 + c];
    red[sub*20 + c] = acc;
    __syncthreads();
    if (t < 20) {
        float s = 0.f;
        #pragma unroll
        for (int w = 0; w < 32; w++) s += red[w*20 + t];
        tot[t] = s;
    }
    __syncthreads();
    if (t < 10) {
        float mu  = tot[t] / (float)NROWS;
        float var = tot[10 + t] / (float)NROWS - mu*mu;
        float a   = g[t] * rsqrtf(var + EPS_BN);
        coef[t]      = a;
        coef[10 + t] = be[t] - mu*a;
    }
}

__global__ void k_fin1(const float* __restrict__ g1, const float* __restrict__ be1)
{ fin_body(g_part1, NB1, g1, be1, g_coef1); }

__global__ void k_fin2(const float* __restrict__ g2, const float* __restrict__ be2)
{ fin_body(g_part2, NB3, g2, be2, g_coef2); }

// =====================================================================
// Kernel 3: BN1 + relu + GEMM2 + stats2  (float2 I/O)
// =====================================================================
__global__ void __launch_bounds__(TPB) k_mlp2(const float* __restrict__ W2,
                                              const float* __restrict__ b2)
{
    __shared__ float sW2[100], sB2[10], sA[10], sC[10], sRed[(TPB/32)*20];
    const int t = threadIdx.x;
    if (t < 100) sW2[t] = W2[t];
    if (t < 10) { sB2[t] = b2[t]; sA[t] = g_coef1[t]; sC[t] = g_coef1[10+t]; }
    __syncthreads();

    const size_t row = (size_t)blockIdx.x*TPB + t;
    const float2* src2 = (const float2*)(g_h1 + row*10);

    float h[10];
    #pragma unroll
    for (int c = 0; c < 5; c++) {
        float2 v = src2[c];
        h[2*c+0] = fmaxf(fmaf(v.x, sA[2*c+0], sC[2*c+0]), 0.f);
        h[2*c+1] = fmaxf(fmaf(v.y, sA[2*c+1], sC[2*c+1]), 0.f);
    }

    float sum[10], sq[10];
    float2* dst2 = (float2*)(g_h2 + row*10);
    #pragma unroll
    for (int c2 = 0; c2 < 10; c2++) {
        float z = sB2[c2];
        #pragma unroll
        for (int c = 0; c < 10; c++) z = fmaf(h[c], sW2[c*10 + c2], z);
        sum[c2] = z;
        sq[c2]  = z*z;
    }
    #pragma unroll
    for (int c = 0; c < 5; c++) dst2[c] = make_float2(sum[2*c], sum[2*c+1]);

    #pragma unroll
    for (int c = 0; c < 10; c++) {
        #pragma unroll
        for (int o = 16; o > 0; o >>= 1) {
            sum[c] += __shfl_down_sync(0xffffffffu, sum[c], o);
            sq[c]  += __shfl_down_sync(0xffffffffu, sq[c],  o);
        }
    }
    const int warp = t >> 5, lane = t & 31;
    if (lane == 0) {
        #pragma unroll
        for (int c = 0; c < 10; c++) {
            sRed[warp*20 + c]      = sum[c];
            sRed[warp*20 + 10 + c] = sq[c];
        }
    }
    __syncthreads();
    if (t < 20) {
        float acc = 0.f;
        #pragma unroll
        for (int w = 0; w < TPB/32; w++) acc += sRed[w*20 + t];
        g_part2[blockIdx.x*20 + t] = acc;
    }
}

// =====================================================================
// Kernel 5: BN2 + relu + max over k  (float2 I/O)
// =====================================================================
__global__ void __launch_bounds__(TPB) k_out(float* __restrict__ out)
{
    __shared__ float sA[10], sC[10];
    if (threadIdx.x < 10) { sA[threadIdx.x] = g_coef2[threadIdx.x]; sC[threadIdx.x] = g_coef2[10+threadIdx.x]; }
    __syncthreads();

    const size_t p = (size_t)blockIdx.x*TPB + threadIdx.x;
    const float2* src2 = (const float2*)(g_h2 + p*KNN*10);

    float mx[10];
    #pragma unroll
    for (int c = 0; c < 10; c++) mx[c] = 0.f;

    #pragma unroll
    for (int i = 0; i < KNN; i++) {
        #pragma unroll
        for (int c = 0; c < 5; c++) {
            float2 v = src2[i*5 + c];
            mx[2*c+0] = fmaxf(mx[2*c+0], fmaxf(fmaf(v.x, sA[2*c+0], sC[2*c+0]), 0.f));
            mx[2*c+1] = fmaxf(mx[2*c+1], fmaxf(fmaf(v.y, sA[2*c+1], sC[2*c+1]), 0.f));
        }
    }
    float2* o2 = (float2*)(out + p*10);
    #pragma unroll
    for (int c = 0; c < 5; c++) o2[c] = make_float2(mx[2*c], mx[2*c+1]);
}

// =====================================================================
extern "C" void kernel_launch(void* const* d_in, const int* in_sizes, int n_in,
                              void* d_out, int out_size)
{
    const float* x   = (const float*)d_in[0];
    const float* W1  = (const float*)d_in[1];
    const float* b1  = (const float*)d_in[2];
    const float* g1  = (const float*)d_in[3];
    const float* be1 = (const float*)d_in[4];
    const float* W2  = (const float*)d_in[5];
    const float* b2  = (const float*)d_in[6];
    const float* g2  = (const float*)d_in[7];
    const float* be2 = (const float*)d_in[8];
    float* out = (float*)d_out;

    const size_t smemSort = (size_t)(3*KB_ + 32 + NPTS)*sizeof(unsigned)
                          + (size_t)NPTS*sizeof(unsigned short);                 // ~72.2KB
    const size_t smemKnn  = (size_t)(NPTS + 2*PAD)*sizeof(float4)
                          + (size_t)NPTS*sizeof(unsigned short)
                          + (size_t)KTPB*sizeof(float);                          // ~146.3KB
    cudaFuncSetAttribute(k_csort, cudaFuncAttributeMaxDynamicSharedMemorySize, (int)smemSort);
    cudaFuncSetAttribute(k_knn,   cudaFuncAttributeMaxDynamicSharedMemorySize, (int)smemKnn);

    k_csort<<<B_, 1024, smemSort>>>(x);
    k_nop<<<1, 32>>>();                       // slot shifters: keep k_knn in the
    k_nop<<<1, 32>>>();                       // ncu capture window (4th launch)
    k_knn<<<NPOINTS/QPBK, KTPB, smemKnn>>>();
    k_feat<<<NB1, TPB>>>(x, W1, b1);
    k_fin1<<<1, 640>>>(g1, be1);
    k_mlp2<<<NB3, TPB>>>(W2, b2);
    k_fin2<<<1, 640>>>(g2, be2);
    k_out<<<NPOINTS/TPB, TPB>>>(out);
}

// round 15
// speedup vs baseline: 2.7971x; 2.7971x over previous
#include <cuda_runtime.h>
#include <math.h>

#define B_    4
#define NPTS  8192
#define KNN   9
#define TPB   256
#define WPAD  64                   // sentinel pad each side (covers +/-63 overhang)
#define BNDMAX 1e37f
#define KB_   2048                 // counting-sort buckets
#define NPOINTS (B_*NPTS)          // 32768
#define NROWS   (NPOINTS*KNN)      // 294912
#define NB1     (NPOINTS/TPB)      // 128
#define NB3     (NROWS/TPB)        // 1152
#define EPS_BN  1e-5f

// ---- scratch (static device memory; no allocations) ----
__device__ float4   g_sp[NPOINTS];                 // sorted points (x,y,z,|p|^2)
__device__ int      g_sid[NPOINTS];                // sorted pos -> original id
__device__ int      g_nbr[(size_t)NPOINTS*KNN];
__device__ __align__(16) float g_h1[(size_t)NROWS*10];
__device__ __align__(16) float g_h2[(size_t)NROWS*10];
__device__ float g_part1[NB1*20];
__device__ float g_part2[NB3*20];
__device__ float g_coef1[20];
__device__ float g_coef2[20];
__device__ int   g_dummy;

// no-op slot-shifter so ncu's fixed capture slot lands on k_knn
__global__ void k_nop() {
    if (threadIdx.x == 1024) g_dummy = 1;
}

// =====================================================================
// Kernel 0: per-batch COUNTING sort by x (exact final order by (x,id))
// =====================================================================
__global__ void __launch_bounds__(1024) k_csort(const float* __restrict__ x)
{
    extern __shared__ unsigned char smem_raw[];
    unsigned*       hist  = (unsigned*)smem_raw;               // [KB_]
    unsigned*       offs  = hist + KB_;                        // [KB_]
    unsigned*       cur   = offs + KB_;                        // [KB_]
    unsigned*       chunk = cur  + KB_;                        // [32]
    float*          keyx  = (float*)(chunk + 32);              // [NPTS]
    unsigned short* kid   = (unsigned short*)(keyx + NPTS);    // [NPTS]

    const int b = blockIdx.x;
    const int t = threadIdx.x;
    const float* xb = x + (size_t)b*NPTS*3;

    for (int i = t; i < KB_; i += 1024) { hist[i] = 0u; cur[i] = 0u; }
    __syncthreads();

    const float lo = -6.f;
    const float invw = (float)KB_ / 12.f;

    for (int i = t; i < NPTS; i += 1024) {
        float px = xb[3*i];
        int bi = (int)floorf((px - lo) * invw);
        bi = min(max(bi, 0), KB_-1);
        atomicAdd(&hist[bi], 1u);
    }
    __syncthreads();

    if (t < 32) {
        unsigned s = 0;
        for (int j = 0; j < 64; j++) s += hist[t*64 + j];
        chunk[t] = s;
    }
    __syncthreads();
    if (t == 0) {
        unsigned s = 0;
        for (int j = 0; j < 32; j++) { unsigned c = chunk[j]; chunk[j] = s; s += c; }
    }
    __syncthreads();
    if (t < 32) {
        unsigned s = chunk[t];
        for (int j = 0; j < 64; j++) { unsigned c = hist[t*64 + j]; offs[t*64 + j] = s; s += c; }
    }
    __syncthreads();

    for (int i = t; i < NPTS; i += 1024) {
        float px = xb[3*i];
        int bi = (int)floorf((px - lo) * invw);
        bi = min(max(bi, 0), KB_-1);
        unsigned slot = offs[bi] + atomicAdd(&cur[bi], 1u);
        keyx[slot] = px;
        kid[slot]  = (unsigned short)i;
    }
    __syncthreads();

    for (int bb = t; bb < KB_; bb += 1024) {
        int s0 = (int)offs[bb];
        int s1 = s0 + (int)hist[bb];
        for (int i2 = s0 + 1; i2 < s1; i2++) {
            float kx = keyx[i2]; unsigned short ki = kid[i2];
            int j = i2 - 1;
            while (j >= s0 && (keyx[j] > kx || (keyx[j] == kx && kid[j] > ki))) {
                keyx[j+1] = keyx[j]; kid[j+1] = kid[j]; j--;
            }
            keyx[j+1] = kx; kid[j+1] = ki;
        }
    }
    __syncthreads();

    for (int i = t; i < NPTS; i += 1024) {
        int id = (int)kid[i];
        float px = xb[3*id+0], py = xb[3*id+1], pz = xb[3*id+2];
        g_sp[(size_t)b*NPTS + i] = make_float4(px, py, pz, px*px + py*py + pz*pz);
        g_sid[(size_t)b*NPTS + i] = id;
    }
}

// =====================================================================
// Kernel A: kNN — ONE WARP PER QUERY, distributed register top-10.
//   Lane j (j<10) holds rank-j (value, original id). All control flow
//   is warp-uniform. 32 candidates per step, one per lane.
// =====================================================================
__global__ void __launch_bounds__(1024, 1) k_knn()
{
    extern __shared__ unsigned char smem_raw[];
    float4*         spb  = (float4*)smem_raw;                 // [NPTS + 2*WPAD]
    float4*         sp   = spb + WPAD;
    unsigned short* ssid = (unsigned short*)(spb + NPTS + 2*WPAD);

    const int t    = threadIdx.x;
    const int lane = t & 31;
    const int warp = t >> 5;                                   // 0..31
    const int blk  = blockIdx.x;
    const int b    = blk >> 8;                                 // 4 batches x 256 blocks
    const int pos  = (blk & 255) * 32 + warp;                  // this warp's query

    for (int i = t; i < NPTS; i += 1024) {
        sp[i]   = g_sp[(size_t)b*NPTS + i];
        ssid[i] = (unsigned short)g_sid[(size_t)b*NPTS + i];
    }
    if (t < WPAD) {
        // w=+inf: never inserted (inf <= s9 false); x=2e19: dx^2=inf > bnd stops scan
        float4 sent = make_float4(2e19f, 0.f, 0.f, __int_as_float(0x7f800000));
        spb[t]        = sent;
        sp[NPTS + t]  = sent;
    }
    __syncthreads();

    const unsigned FULL = 0xffffffffu;
    const float4 q = sp[pos];
    const float qq  = q.w;
    const float nqx = -2.f*q.x, nqy = -2.f*q.y, nqz = -2.f*q.z;

    // distributed sorted top-10: lane j holds rank j (ascending by (v,id))
    float v   = 3.4e38f;  int idv = 0x7fffffff;
    float s9  = 3.4e38f;  int id9 = 0x7fffffff;    // rank-9 entry, in every lane
    float bnd = BNDMAX;

    int rbase = pos, lbase = pos - 1;
    bool goR = true, goL = true;

    #pragma unroll 1
    while (goR || goL) {
        #pragma unroll 1
        for (int dir = 0; dir < 2; dir++) {
            const bool active = dir ? goL : goR;
            if (!active) continue;                 // warp-uniform
            const int cpos = dir ? (lbase - lane) : (rbase + lane);
            float4 p = sp[cpos];
            float dx = p.x - q.x;
            float sv = fmaf(p.z,nqz,fmaf(p.y,nqy,fmaf(p.x,nqx,p.w)));
            // lane 0 is nearest in x for both directions
            int fail0 = __shfl_sync(FULL, (dx*dx > bnd) ? 1 : 0, 0);
            if (fail0) { if (dir) goL = false; else goR = false; continue; }

            unsigned m = __ballot_sync(FULL, sv <= s9);
            #pragma unroll 1
            while (m) {
                int k = __ffs(m) - 1; m &= m - 1;
                float nv  = __shfl_sync(FULL, sv, k);
                int  npos = __shfl_sync(FULL, cpos, k);
                int  nid  = (int)ssid[npos];       // same addr all lanes: broadcast
                if (nv < s9 || (nv == s9 && nid < id9)) {   // warp-uniform
                    bool ins = (nv < v) || (nv == v && nid < idv);
                    unsigned bm = __ballot_sync(FULL, ins);
                    int kk = __ffs(bm) - 1;        // <= 9 guaranteed by pre-check
                    float vp = __shfl_up_sync(FULL, v, 1);
                    int   ip = __shfl_up_sync(FULL, idv, 1);
                    if (lane > kk)       { v = vp; idv = ip; }
                    else if (lane == kk) { v = nv; idv = nid; }
                    s9  = __shfl_sync(FULL, v, 9);
                    id9 = __shfl_sync(FULL, idv, 9);
                    bnd = fminf(fmaf(s9 + qq, 1.01f, 4e-6f), BNDMAX);
                }
            }
            if (dir) lbase -= 32; else rbase += 32;
        }
    }

    // rank 0 = self (d2 ~ 0, strict minimum); reference keeps ranks 1..9
    const int qoid = (int)ssid[pos];
    if (lane >= 1 && lane <= 9)
        g_nbr[(size_t)(b*NPTS + qoid)*KNN + (lane - 1)] = idv;
}

// =====================================================================
// Kernel B: angular features + GEMM1 + stats1
// =====================================================================
__global__ void __launch_bounds__(TPB) k_feat(const float* __restrict__ x,
                                              const float* __restrict__ W1,
                                              const float* __restrict__ b1)
{
    __shared__ float sW1[70], sB1[10], sRed[(TPB/32)*20];
    const int t = threadIdx.x;
    if (t < 70) sW1[t] = W1[t];
    if (t < 10) sB1[t] = b1[t];
    __syncthreads();

    const int p = blockIdx.x*TPB + t;
    const int b = p / NPTS;
    const int n = p % NPTS;
    const float* xb = x + (size_t)b*NPTS*3;
    const float qx = xb[3*n+0], qy = xb[3*n+1], qz = xb[3*n+2];

    const int* ids = g_nbr + (size_t)p*KNN;
    float rx[KNN], ry[KNN], rz[KNN], ph[KNN];
    #pragma unroll
    for (int j = 0; j < KNN; j++) {
        int id = ids[j];
        rx[j] = xb[3*id+0] - qx;
        ry[j] = xb[3*id+1] - qy;
        rz[j] = xb[3*id+2] - qz;
        ph[j] = atan2f(ry[j], rx[j]);
    }

    #pragma unroll
    for (int pass = 0; pass < KNN-1; pass++) {
        #pragma unroll
        for (int j = 0; j < KNN-1; j++) {
            if (j < KNN-1-pass) {
                if (ph[j+1] < ph[j]) {
                    float tt;
                    tt = ph[j]; ph[j] = ph[j+1]; ph[j+1] = tt;
                    tt = rx[j]; rx[j] = rx[j+1]; rx[j+1] = tt;
                    tt = ry[j]; ry[j] = ry[j+1]; ry[j+1] = tt;
                    tt = rz[j]; rz[j] = rz[j+1]; rz[j+1] = tt;
                }
            }
        }
    }

    float sum[10], sq[10];
    #pragma unroll
    for (int c = 0; c < 10; c++) { sum[c] = 0.f; sq[c] = 0.f; }

    float sgn = 1.f;
    const size_t rowbase = (size_t)p * KNN * 10;
    #pragma unroll
    for (int i = 0; i < KNN; i++) {
        const int i2 = (i+1) % KNN;
        float v1x = rx[i],  v1y = ry[i],  v1z = rz[i];
        float v2x = rx[i2], v2y = ry[i2], v2z = rz[i2];
        float cx = 0.5f*(v1x+v2x), cy = 0.5f*(v1y+v2y), cz = 0.5f*(v1z+v2z);
        float nx = v1y*v2z - v1z*v2y;
        float ny = v1z*v2x - v1x*v2z;
        float nz = v1x*v2y - v1y*v2x;
        float nrm = sqrtf(nx*nx + ny*ny + nz*nz);
        float inv = 1.f/(nrm + 1e-6f);
        nx *= inv; ny *= inv; nz *= inv;
        if (i == 0) sgn = (nx > 0.f) ? 1.f : -1.f;
        nx *= sgn; ny *= sgn; nz *= sgn;
        float pos7 = (nx*cx + ny*cy + nz*cz) * 0.57735026918962576f;

        float f[7] = {cx, cy, cz, nx, ny, nz, pos7};
        #pragma unroll
        for (int c = 0; c < 10; c++) {
            float h = sB1[c];
            #pragma unroll
            for (int ff = 0; ff < 7; ff++) h = fmaf(f[ff], sW1[ff*10 + c], h);
            g_h1[rowbase + i*10 + c] = h;
            sum[c] += h;
            sq[c]  = fmaf(h, h, sq[c]);
        }
    }

    #pragma unroll
    for (int c = 0; c < 10; c++) {
        #pragma unroll
        for (int o = 16; o > 0; o >>= 1) {
            sum[c] += __shfl_down_sync(0xffffffffu, sum[c], o);
            sq[c]  += __shfl_down_sync(0xffffffffu, sq[c],  o);
        }
    }
    const int warp = t >> 5, lane = t & 31;
    if (lane == 0) {
        #pragma unroll
        for (int c = 0; c < 10; c++) {
            sRed[warp*20 + c]      = sum[c];
            sRed[warp*20 + 10 + c] = sq[c];
        }
    }
    __syncthreads();
    if (t < 20) {
        float acc = 0.f;
        #pragma unroll
        for (int w = 0; w < TPB/32; w++) acc += sRed[w*20 + t];
        g_part1[blockIdx.x*20 + t] = acc;
    }
}

// =====================================================================
// Parallel BN-stats finalize
// =====================================================================
__device__ __forceinline__ void fin_body(const float* __restrict__ part, int nblk,
                                         const float* __restrict__ g,
                                         const float* __restrict__ be,
                                         float* __restrict__ coef)
{
    __shared__ float red[32*20];
    __shared__ float tot[20];
    const int t = threadIdx.x;
    const int c = t % 20, sub = t / 20;
    float acc = 0.f;
    for (int k = sub; k < nblk; k += 32) acc += part[k*20 + c];
    red[sub*20 + c] = acc;
    __syncthreads();
    if (t < 20) {
        float s = 0.f;
        #pragma unroll
        for (int w = 0; w < 32; w++) s += red[w*20 + t];
        tot[t] = s;
    }
    __syncthreads();
    if (t < 10) {
        float mu  = tot[t] / (float)NROWS;
        float var = tot[10 + t] / (float)NROWS - mu*mu;
        float a   = g[t] * rsqrtf(var + EPS_BN);
        coef[t]      = a;
        coef[10 + t] = be[t] - mu*a;
    }
}

__global__ void k_fin1(const float* __restrict__ g1, const float* __restrict__ be1)
{ fin_body(g_part1, NB1, g1, be1, g_coef1); }

__global__ void k_fin2(const float* __restrict__ g2, const float* __restrict__ be2)
{ fin_body(g_part2, NB3, g2, be2, g_coef2); }

// =====================================================================
// Kernel 3: BN1 + relu + GEMM2 + stats2  (float2 I/O)
// =====================================================================
__global__ void __launch_bounds__(TPB) k_mlp2(const float* __restrict__ W2,
                                              const float* __restrict__ b2)
{
    __shared__ float sW2[100], sB2[10], sA[10], sC[10], sRed[(TPB/32)*20];
    const int t = threadIdx.x;
    if (t < 100) sW2[t] = W2[t];
    if (t < 10) { sB2[t] = b2[t]; sA[t] = g_coef1[t]; sC[t] = g_coef1[10+t]; }
    __syncthreads();

    const size_t row = (size_t)blockIdx.x*TPB + t;
    const float2* src2 = (const float2*)(g_h1 + row*10);

    float h[10];
    #pragma unroll
    for (int c = 0; c < 5; c++) {
        float2 v = src2[c];
        h[2*c+0] = fmaxf(fmaf(v.x, sA[2*c+0], sC[2*c+0]), 0.f);
        h[2*c+1] = fmaxf(fmaf(v.y, sA[2*c+1], sC[2*c+1]), 0.f);
    }

    float sum[10], sq[10];
    float2* dst2 = (float2*)(g_h2 + row*10);
    #pragma unroll
    for (int c2 = 0; c2 < 10; c2++) {
        float z = sB2[c2];
        #pragma unroll
        for (int c = 0; c < 10; c++) z = fmaf(h[c], sW2[c*10 + c2], z);
        sum[c2] = z;
        sq[c2]  = z*z;
    }
    #pragma unroll
    for (int c = 0; c < 5; c++) dst2[c] = make_float2(sum[2*c], sum[2*c+1]);

    #pragma unroll
    for (int c = 0; c < 10; c++) {
        #pragma unroll
        for (int o = 16; o > 0; o >>= 1) {
            sum[c] += __shfl_down_sync(0xffffffffu, sum[c], o);
            sq[c]  += __shfl_down_sync(0xffffffffu, sq[c],  o);
        }
    }
    const int warp = t >> 5, lane = t & 31;
    if (lane == 0) {
        #pragma unroll
        for (int c = 0; c < 10; c++) {
            sRed[warp*20 + c]      = sum[c];
            sRed[warp*20 + 10 + c] = sq[c];
        }
    }
    __syncthreads();
    if (t < 20) {
        float acc = 0.f;
        #pragma unroll
        for (int w = 0; w < TPB/32; w++) acc += sRed[w*20 + t];
        g_part2[blockIdx.x*20 + t] = acc;
    }
}

// =====================================================================
// Kernel 5: BN2 + relu + max over k  (float2 I/O)
// =====================================================================
__global__ void __launch_bounds__(TPB) k_out(float* __restrict__ out)
{
    __shared__ float sA[10], sC[10];
    if (threadIdx.x < 10) { sA[threadIdx.x] = g_coef2[threadIdx.x]; sC[threadIdx.x] = g_coef2[10+threadIdx.x]; }
    __syncthreads();

    const size_t p = (size_t)blockIdx.x*TPB + threadIdx.x;
    const float2* src2 = (const float2*)(g_h2 + p*KNN*10);

    float mx[10];
    #pragma unroll
    for (int c = 0; c < 10; c++) mx[c] = 0.f;

    #pragma unroll
    for (int i = 0; i < KNN; i++) {
        #pragma unroll
        for (int c = 0; c < 5; c++) {
            float2 v = src2[i*5 + c];
            mx[2*c+0] = fmaxf(mx[2*c+0], fmaxf(fmaf(v.x, sA[2*c+0], sC[2*c+0]), 0.f));
            mx[2*c+1] = fmaxf(mx[2*c+1], fmaxf(fmaf(v.y, sA[2*c+1], sC[2*c+1]), 0.f));
        }
    }
    float2* o2 = (float2*)(out + p*10);
    #pragma unroll
    for (int c = 0; c < 5; c++) o2[c] = make_float2(mx[2*c], mx[2*c+1]);
}

// =====================================================================
extern "C" void kernel_launch(void* const* d_in, const int* in_sizes, int n_in,
                              void* d_out, int out_size)
{
    const float* x   = (const float*)d_in[0];
    const float* W1  = (const float*)d_in[1];
    const float* b1  = (const float*)d_in[2];
    const float* g1  = (const float*)d_in[3];
    const float* be1 = (const float*)d_in[4];
    const float* W2  = (const float*)d_in[5];
    const float* b2  = (const float*)d_in[6];
    const float* g2  = (const float*)d_in[7];
    const float* be2 = (const float*)d_in[8];
    float* out = (float*)d_out;

    const size_t smemSort = (size_t)(3*KB_ + 32 + NPTS)*sizeof(unsigned)
                          + (size_t)NPTS*sizeof(unsigned short);                 // ~72.2KB
    const size_t smemKnn  = (size_t)(NPTS + 2*WPAD)*sizeof(float4)
                          + (size_t)NPTS*sizeof(unsigned short);                 // ~146KB
    cudaFuncSetAttribute(k_csort, cudaFuncAttributeMaxDynamicSharedMemorySize, (int)smemSort);
    cudaFuncSetAttribute(k_knn,   cudaFuncAttributeMaxDynamicSharedMemorySize, (int)smemKnn);

    k_csort<<<B_, 1024, smemSort>>>(x);
    k_nop<<<1, 32>>>();                       // slot shifters: keep k_knn in the
    k_nop<<<1, 32>>>();                       // ncu capture window (4th launch)
    k_knn<<<NPOINTS/32, 1024, smemKnn>>>();
    k_feat<<<NB1, TPB>>>(x, W1, b1);
    k_fin1<<<1, 640>>>(g1, be1);
    k_mlp2<<<NB3, TPB>>>(W2, b2);
    k_fin2<<<1, 640>>>(g2, be2);
    k_out<<<NPOINTS/TPB, TPB>>>(out);
}

// round 16
// speedup vs baseline: 3.1147x; 1.1136x over previous
#include <cuda_runtime.h>
#include <math.h>

#define B_    4
#define NPTS  8192
#define KNN   9
#define TPB   256
#define WPAD  64                   // sentinel pad each side (covers +/-63 overhang)
#define BNDMAX 1e37f
#define KB_   2048                 // counting-sort buckets
#define NPOINTS (B_*NPTS)          // 32768
#define NROWS   (NPOINTS*KNN)      // 294912
#define NB1     (NPOINTS/TPB)      // 128
#define NB3     (NROWS/TPB)        // 1152
#define EPS_BN  1e-5f

// ---- scratch (static device memory; no allocations) ----
__device__ float4   g_sp[NPOINTS];                 // sorted points (x,y,z,|p|^2)
__device__ int      g_sid[NPOINTS];                // sorted pos -> original id
__device__ int      g_nbr[(size_t)NPOINTS*KNN];
__device__ __align__(16) float g_h1[(size_t)NROWS*10];
__device__ __align__(16) float g_h2[(size_t)NROWS*10];
__device__ float g_part1[NB1*20];
__device__ float g_part2[NB3*20];
__device__ float g_coef1[20];
__device__ float g_coef2[20];
__device__ int   g_dummy;

// no-op slot-shifter so ncu's fixed capture slot lands on k_knn
__global__ void k_nop() {
    if (threadIdx.x == 1024) g_dummy = 1;
}

// =====================================================================
// Kernel 0: per-batch COUNTING sort by x (exact final order by (x,id))
// =====================================================================
__global__ void __launch_bounds__(1024) k_csort(const float* __restrict__ x)
{
    extern __shared__ unsigned char smem_raw[];
    unsigned*       hist  = (unsigned*)smem_raw;               // [KB_]
    unsigned*       offs  = hist + KB_;                        // [KB_]
    unsigned*       cur   = offs + KB_;                        // [KB_]
    unsigned*       chunk = cur  + KB_;                        // [32]
    float*          keyx  = (float*)(chunk + 32);              // [NPTS]
    unsigned short* kid   = (unsigned short*)(keyx + NPTS);    // [NPTS]

    const int b = blockIdx.x;
    const int t = threadIdx.x;
    const float* xb = x + (size_t)b*NPTS*3;

    for (int i = t; i < KB_; i += 1024) { hist[i] = 0u; cur[i] = 0u; }
    __syncthreads();

    const float lo = -6.f;
    const float invw = (float)KB_ / 12.f;

    for (int i = t; i < NPTS; i += 1024) {
        float px = xb[3*i];
        int bi = (int)floorf((px - lo) * invw);
        bi = min(max(bi, 0), KB_-1);
        atomicAdd(&hist[bi], 1u);
    }
    __syncthreads();

    if (t < 32) {
        unsigned s = 0;
        for (int j = 0; j < 64; j++) s += hist[t*64 + j];
        chunk[t] = s;
    }
    __syncthreads();
    if (t == 0) {
        unsigned s = 0;
        for (int j = 0; j < 32; j++) { unsigned c = chunk[j]; chunk[j] = s; s += c; }
    }
    __syncthreads();
    if (t < 32) {
        unsigned s = chunk[t];
        for (int j = 0; j < 64; j++) { unsigned c = hist[t*64 + j]; offs[t*64 + j] = s; s += c; }
    }
    __syncthreads();

    for (int i = t; i < NPTS; i += 1024) {
        float px = xb[3*i];
        int bi = (int)floorf((px - lo) * invw);
        bi = min(max(bi, 0), KB_-1);
        unsigned slot = offs[bi] + atomicAdd(&cur[bi], 1u);
        keyx[slot] = px;
        kid[slot]  = (unsigned short)i;
    }
    __syncthreads();

    for (int bb = t; bb < KB_; bb += 1024) {
        int s0 = (int)offs[bb];
        int s1 = s0 + (int)hist[bb];
        for (int i2 = s0 + 1; i2 < s1; i2++) {
            float kx = keyx[i2]; unsigned short ki = kid[i2];
            int j = i2 - 1;
            while (j >= s0 && (keyx[j] > kx || (keyx[j] == kx && kid[j] > ki))) {
                keyx[j+1] = keyx[j]; kid[j+1] = kid[j]; j--;
            }
            keyx[j+1] = kx; kid[j+1] = ki;
        }
    }
    __syncthreads();

    for (int i = t; i < NPTS; i += 1024) {
        int id = (int)kid[i];
        float px = xb[3*id+0], py = xb[3*id+1], pz = xb[3*id+2];
        g_sp[(size_t)b*NPTS + i] = make_float4(px, py, pz, px*px + py*py + pz*pz);
        g_sid[(size_t)b*NPTS + i] = id;
    }
}

// =====================================================================
// Kernel A: kNN — ONE WARP PER QUERY, distributed register top-10.
//   Bitonic warm-up: sort first 32 right-side candidates by (v,id) to
//   initialize the list + bound; then scan outward with serial events.
// =====================================================================
__global__ void __launch_bounds__(1024, 1) k_knn()
{
    extern __shared__ unsigned char smem_raw[];
    float4*         spb  = (float4*)smem_raw;                 // [NPTS + 2*WPAD]
    float4*         sp   = spb + WPAD;
    unsigned short* ssid = (unsigned short*)(spb + NPTS + 2*WPAD);

    const int t    = threadIdx.x;
    const int lane = t & 31;
    const int warp = t >> 5;                                   // 0..31
    const int blk  = blockIdx.x;
    const int b    = blk >> 8;                                 // 4 batches x 256 blocks
    const int pos  = (blk & 255) * 32 + warp;                  // this warp's query

    for (int i = t; i < NPTS; i += 1024) {
        sp[i]   = g_sp[(size_t)b*NPTS + i];
        ssid[i] = (unsigned short)g_sid[(size_t)b*NPTS + i];
    }
    if (t < WPAD) {
        // w=+inf: never inserted (inf <= s9<=3.4e38 false); x=2e19: dx^2=inf > bnd stops
        float4 sent = make_float4(2e19f, 0.f, 0.f, __int_as_float(0x7f800000));
        spb[t]        = sent;
        sp[NPTS + t]  = sent;
    }
    __syncthreads();

    const unsigned FULL = 0xffffffffu;
    const float4 q = sp[pos];
    const float qq  = q.w;
    const float nqx = -2.f*q.x, nqy = -2.f*q.y, nqz = -2.f*q.z;

    // ---- bitonic warm-up: exact sort of first right group by (v,id) -----
    float v; int idv;
    {
        const int cpos0 = pos + lane;
        if (cpos0 < NPTS) {
            float4 p = sp[cpos0];
            v   = fmaf(p.z,nqz,fmaf(p.y,nqy,fmaf(p.x,nqx,p.w)));
            idv = (int)ssid[cpos0];
        } else {
            v = 3.4e38f; idv = 0x7fffffff;
        }
        #pragma unroll
        for (int k = 2; k <= 32; k <<= 1) {
            #pragma unroll
            for (int j = k >> 1; j > 0; j >>= 1) {
                float ov = __shfl_xor_sync(FULL, v, j);
                int   oi = __shfl_xor_sync(FULL, idv, j);
                bool dirUp  = ((lane & k) == 0);
                bool iAmLow = ((lane & j) == 0);
                bool less = (ov < v) || (ov == v && oi < idv);   // other < mine
                bool take = (dirUp == iAmLow) ? less : !less;
                if (take) { v = ov; idv = oi; }
            }
        }
    }
    float s9  = __shfl_sync(FULL, v, 9);
    int   id9 = __shfl_sync(FULL, idv, 9);
    float bnd = fminf(fmaf(s9 + qq, 1.01f, 4e-6f), BNDMAX);

    int rbase = pos + 32, lbase = pos - 1;
    bool goR = true, goL = true;

    #pragma unroll 1
    while (goR || goL) {
        #pragma unroll 1
        for (int dir = 0; dir < 2; dir++) {
            const bool active = dir ? goL : goR;
            if (!active) continue;                 // warp-uniform
            const int cpos = dir ? (lbase - lane) : (rbase + lane);
            float4 p = sp[cpos];
            float dx = p.x - q.x;
            float sv = fmaf(p.z,nqz,fmaf(p.y,nqy,fmaf(p.x,nqx,p.w)));
            // lane 0 is nearest in x for both directions
            int fail0 = __shfl_sync(FULL, (dx*dx > bnd) ? 1 : 0, 0);
            if (fail0) { if (dir) goL = false; else goR = false; continue; }

            unsigned m = __ballot_sync(FULL, sv <= s9);
            #pragma unroll 1
            while (m) {
                int k = __ffs(m) - 1; m &= m - 1;
                float nv  = __shfl_sync(FULL, sv, k);
                int  npos = __shfl_sync(FULL, cpos, k);
                int  nid  = (int)ssid[npos];       // same addr all lanes: broadcast
                if (nv < s9 || (nv == s9 && nid < id9)) {   // warp-uniform
                    bool ins = (nv < v) || (nv == v && nid < idv);
                    unsigned bm = __ballot_sync(FULL, ins);
                    int kk = __ffs(bm) - 1;        // <= 9 guaranteed by pre-check
                    float vp = __shfl_up_sync(FULL, v, 1);
                    int   ip = __shfl_up_sync(FULL, idv, 1);
                    if (lane > kk)       { v = vp; idv = ip; }
                    else if (lane == kk) { v = nv; idv = nid; }
                    s9  = __shfl_sync(FULL, v, 9);
                    id9 = __shfl_sync(FULL, idv, 9);
                    bnd = fminf(fmaf(s9 + qq, 1.01f, 4e-6f), BNDMAX);
                }
            }
            if (dir) lbase -= 32; else rbase += 32;
        }
    }

    // rank 0 = self (d2 strict minimum); reference keeps ranks 1..9
    const int qoid = (int)ssid[pos];
    if (lane >= 1 && lane <= 9)
        g_nbr[(size_t)(b*NPTS + qoid)*KNN + (lane - 1)] = idv;
}

// =====================================================================
// Kernel B: angular features + GEMM1 + stats1
// =====================================================================
__global__ void __launch_bounds__(TPB) k_feat(const float* __restrict__ x,
                                              const float* __restrict__ W1,
                                              const float* __restrict__ b1)
{
    __shared__ float sW1[70], sB1[10], sRed[(TPB/32)*20];
    const int t = threadIdx.x;
    if (t < 70) sW1[t] = W1[t];
    if (t < 10) sB1[t] = b1[t];
    __syncthreads();

    const int p = blockIdx.x*TPB + t;
    const int b = p / NPTS;
    const int n = p % NPTS;
    const float* xb = x + (size_t)b*NPTS*3;
    const float qx = xb[3*n+0], qy = xb[3*n+1], qz = xb[3*n+2];

    const int* ids = g_nbr + (size_t)p*KNN;
    float rx[KNN], ry[KNN], rz[KNN], ph[KNN];
    #pragma unroll
    for (int j = 0; j < KNN; j++) {
        int id = ids[j];
        rx[j] = xb[3*id+0] - qx;
        ry[j] = xb[3*id+1] - qy;
        rz[j] = xb[3*id+2] - qz;
        ph[j] = atan2f(ry[j], rx[j]);
    }

    #pragma unroll
    for (int pass = 0; pass < KNN-1; pass++) {
        #pragma unroll
        for (int j = 0; j < KNN-1; j++) {
            if (j < KNN-1-pass) {
                if (ph[j+1] < ph[j]) {
                    float tt;
                    tt = ph[j]; ph[j] = ph[j+1]; ph[j+1] = tt;
                    tt = rx[j]; rx[j] = rx[j+1]; rx[j+1] = tt;
                    tt = ry[j]; ry[j] = ry[j+1]; ry[j+1] = tt;
                    tt = rz[j]; rz[j] = rz[j+1]; rz[j+1] = tt;
                }
            }
        }
    }

    float sum[10], sq[10];
    #pragma unroll
    for (int c = 0; c < 10; c++) { sum[c] = 0.f; sq[c] = 0.f; }

    float sgn = 1.f;
    const size_t rowbase = (size_t)p * KNN * 10;
    #pragma unroll
    for (int i = 0; i < KNN; i++) {
        const int i2 = (i+1) % KNN;
        float v1x = rx[i],  v1y = ry[i],  v1z = rz[i];
        float v2x = rx[i2], v2y = ry[i2], v2z = rz[i2];
        float cx = 0.5f*(v1x+v2x), cy = 0.5f*(v1y+v2y), cz = 0.5f*(v1z+v2z);
        float nx = v1y*v2z - v1z*v2y;
        float ny = v1z*v2x - v1x*v2z;
        float nz = v1x*v2y - v1y*v2x;
        float nrm = sqrtf(nx*nx + ny*ny + nz*nz);
        float inv = 1.f/(nrm + 1e-6f);
        nx *= inv; ny *= inv; nz *= inv;
        if (i == 0) sgn = (nx > 0.f) ? 1.f : -1.f;
        nx *= sgn; ny *= sgn; nz *= sgn;
        float pos7 = (nx*cx + ny*cy + nz*cz) * 0.57735026918962576f;

        float f[7] = {cx, cy, cz, nx, ny, nz, pos7};
        #pragma unroll
        for (int c = 0; c < 10; c++) {
            float h = sB1[c];
            #pragma unroll
            for (int ff = 0; ff < 7; ff++) h = fmaf(f[ff], sW1[ff*10 + c], h);
            g_h1[rowbase + i*10 + c] = h;
            sum[c] += h;
            sq[c]  = fmaf(h, h, sq[c]);
        }
    }

    #pragma unroll
    for (int c = 0; c < 10; c++) {
        #pragma unroll
        for (int o = 16; o > 0; o >>= 1) {
            sum[c] += __shfl_down_sync(0xffffffffu, sum[c], o);
            sq[c]  += __shfl_down_sync(0xffffffffu, sq[c],  o);
        }
    }
    const int warp = t >> 5, lane = t & 31;
    if (lane == 0) {
        #pragma unroll
        for (int c = 0; c < 10; c++) {
            sRed[warp*20 + c]      = sum[c];
            sRed[warp*20 + 10 + c] = sq[c];
        }
    }
    __syncthreads();
    if (t < 20) {
        float acc = 0.f;
        #pragma unroll
        for (int w = 0; w < TPB/32; w++) acc += sRed[w*20 + t];
        g_part1[blockIdx.x*20 + t] = acc;
    }
}

// =====================================================================
// Parallel BN-stats finalize
// =====================================================================
__device__ __forceinline__ void fin_body(const float* __restrict__ part, int nblk,
                                         const float* __restrict__ g,
                                         const float* __restrict__ be,
                                         float* __restrict__ coef)
{
    __shared__ float red[32*20];
    __shared__ float tot[20];
    const int t = threadIdx.x;
    const int c = t % 20, sub = t / 20;
    float acc = 0.f;
    for (int k = sub; k < nblk; k += 32) acc += part[k*20 + c];
    red[sub*20 + c] = acc;
    __syncthreads();
    if (t < 20) {
        float s = 0.f;
        #pragma unroll
        for (int w = 0; w < 32; w++) s += red[w*20 + t];
        tot[t] = s;
    }
    __syncthreads();
    if (t < 10) {
        float mu  = tot[t] / (float)NROWS;
        float var = tot[10 + t] / (float)NROWS - mu*mu;
        float a   = g[t] * rsqrtf(var + EPS_BN);
        coef[t]      = a;
        coef[10 + t] = be[t] - mu*a;
    }
}

__global__ void k_fin1(const float* __restrict__ g1, const float* __restrict__ be1)
{ fin_body(g_part1, NB1, g1, be1, g_coef1); }

__global__ void k_fin2(const float* __restrict__ g2, const float* __restrict__ be2)
{ fin_body(g_part2, NB3, g2, be2, g_coef2); }

// =====================================================================
// Kernel 3: BN1 + relu + GEMM2 + stats2  (float2 I/O)
// =====================================================================
__global__ void __launch_bounds__(TPB) k_mlp2(const float* __restrict__ W2,
                                              const float* __restrict__ b2)
{
    __shared__ float sW2[100], sB2[10], sA[10], sC[10], sRed[(TPB/32)*20];
    const int t = threadIdx.x;
    if (t < 100) sW2[t] = W2[t];
    if (t < 10) { sB2[t] = b2[t]; sA[t] = g_coef1[t]; sC[t] = g_coef1[10+t]; }
    __syncthreads();

    const size_t row = (size_t)blockIdx.x*TPB + t;
    const float2* src2 = (const float2*)(g_h1 + row*10);

    float h[10];
    #pragma unroll
    for (int c = 0; c < 5; c++) {
        float2 v = src2[c];
        h[2*c+0] = fmaxf(fmaf(v.x, sA[2*c+0], sC[2*c+0]), 0.f);
        h[2*c+1] = fmaxf(fmaf(v.y, sA[2*c+1], sC[2*c+1]), 0.f);
    }

    float sum[10], sq[10];
    float2* dst2 = (float2*)(g_h2 + row*10);
    #pragma unroll
    for (int c2 = 0; c2 < 10; c2++) {
        float z = sB2[c2];
        #pragma unroll
        for (int c = 0; c < 10; c++) z = fmaf(h[c], sW2[c*10 + c2], z);
        sum[c2] = z;
        sq[c2]  = z*z;
    }
    #pragma unroll
    for (int c = 0; c < 5; c++) dst2[c] = make_float2(sum[2*c], sum[2*c+1]);

    #pragma unroll
    for (int c = 0; c < 10; c++) {
        #pragma unroll
        for (int o = 16; o > 0; o >>= 1) {
            sum[c] += __shfl_down_sync(0xffffffffu, sum[c], o);
            sq[c]  += __shfl_down_sync(0xffffffffu, sq[c],  o);
        }
    }
    const int warp = t >> 5, lane = t & 31;
    if (lane == 0) {
        #pragma unroll
        for (int c = 0; c < 10; c++) {
            sRed[warp*20 + c]      = sum[c];
            sRed[warp*20 + 10 + c] = sq[c];
        }
    }
    __syncthreads();
    if (t < 20) {
        float acc = 0.f;
        #pragma unroll
        for (int w = 0; w < TPB/32; w++) acc += sRed[w*20 + t];
        g_part2[blockIdx.x*20 + t] = acc;
    }
}

// =====================================================================
// Kernel 5: BN2 + relu + max over k  (float2 I/O)
// =====================================================================
__global__ void __launch_bounds__(TPB) k_out(float* __restrict__ out)
{
    __shared__ float sA[10], sC[10];
    if (threadIdx.x < 10) { sA[threadIdx.x] = g_coef2[threadIdx.x]; sC[threadIdx.x] = g_coef2[10+threadIdx.x]; }
    __syncthreads();

    const size_t p = (size_t)blockIdx.x*TPB + threadIdx.x;
    const float2* src2 = (const float2*)(g_h2 + p*KNN*10);

    float mx[10];
    #pragma unroll
    for (int c = 0; c < 10; c++) mx[c] = 0.f;

    #pragma unroll
    for (int i = 0; i < KNN; i++) {
        #pragma unroll
        for (int c = 0; c < 5; c++) {
            float2 v = src2[i*5 + c];
            mx[2*c+0] = fmaxf(mx[2*c+0], fmaxf(fmaf(v.x, sA[2*c+0], sC[2*c+0]), 0.f));
            mx[2*c+1] = fmaxf(mx[2*c+1], fmaxf(fmaf(v.y, sA[2*c+1], sC[2*c+1]), 0.f));
        }
    }
    float2* o2 = (float2*)(out + p*10);
    #pragma unroll
    for (int c = 0; c < 5; c++) o2[c] = make_float2(mx[2*c], mx[2*c+1]);
}

// =====================================================================
extern "C" void kernel_launch(void* const* d_in, const int* in_sizes, int n_in,
                              void* d_out, int out_size)
{
    const float* x   = (const float*)d_in[0];
    const float* W1  = (const float*)d_in[1];
    const float* b1  = (const float*)d_in[2];
    const float* g1  = (const float*)d_in[3];
    const float* be1 = (const float*)d_in[4];
    const float* W2  = (const float*)d_in[5];
    const float* b2  = (const float*)d_in[6];
    const float* g2  = (const float*)d_in[7];
    const float* be2 = (const float*)d_in[8];
    float* out = (float*)d_out;

    const size_t smemSort = (size_t)(3*KB_ + 32 + NPTS)*sizeof(unsigned)
                          + (size_t)NPTS*sizeof(unsigned short);                 // ~72.2KB
    const size_t smemKnn  = (size_t)(NPTS + 2*WPAD)*sizeof(float4)
                          + (size_t)NPTS*sizeof(unsigned short);                 // ~146KB
    cudaFuncSetAttribute(k_csort, cudaFuncAttributeMaxDynamicSharedMemorySize, (int)smemSort);
    cudaFuncSetAttribute(k_knn,   cudaFuncAttributeMaxDynamicSharedMemorySize, (int)smemKnn);

    k_csort<<<B_, 1024, smemSort>>>(x);
    k_nop<<<1, 32>>>();                       // slot shifters: keep k_knn in the
    k_nop<<<1, 32>>>();                       // ncu capture window (4th launch)
    k_knn<<<NPOINTS/32, 1024, smemKnn>>>();
    k_feat<<<NB1, TPB>>>(x, W1, b1);
    k_fin1<<<1, 640>>>(g1, be1);
    k_mlp2<<<NB3, TPB>>>(W2, b2);
    k_fin2<<<1, 640>>>(g2, be2);
    k_out<<<NPOINTS/TPB, TPB>>>(out);
}